// round 13
// baseline (speedup 1.0000x reference)
#include <cuda_runtime.h>
#include <math_constants.h>
#include <stdint.h>

// MulticlassNMS v6 — global-threshold pruning, single tiny tail block.
// K1 hist_kernel:   2048-bin histogram of fg scores > conf (coalesced).
// K2 thresh_kernel: scan hist -> g_t (~1024..2048 survivors), g_t300 (~384),
//                   reset candidate counter, zero hist for next replay.
// K3 compact_kernel: ballot-compact all scores > g_t into packed keys
//                   (cls<<45 | scorebits<<13 | idx).
// K4 process_kernel (1 block, 1024 thr): sort keys (class/score/idx desc),
//                   per-warp NMS per class (M<=32 register path; block path
//                   for bigger classes), keeps -> g_fb, select via t300,
//                   sort 512, write preds+labels. Exact fallback path for
//                   candidate overflow / keep shortfall (never taken here).

#define MAXK     300
#define HBINS    2048
#define CAND_CAP 4096
#define TB       1024
#define FULLM    0xffffffffu

__device__ int                g_hist[HBINS];
__device__ float              g_t, g_t300;
__device__ int                g_nc;
__device__ unsigned long long g_cand[CAND_CAP];
__device__ unsigned long long g_fb[24064];

// exact IoU>thr: multiply filter, __fdiv_rn fallback in ~1e-4 boundary band
__device__ __forceinline__ bool iou_gt(const float4 a, float aa,
                                       const float4 b, float ba,
                                       float thr, float thrLo, float thrHi)
{
    float ix1 = fmaxf(a.x, b.x), iy1 = fmaxf(a.y, b.y);
    float ix2 = fminf(a.z, b.z), iy2 = fminf(a.w, b.w);
    float iw = ix2 - ix1, ih = iy2 - iy1;
    if (iw <= 0.f || ih <= 0.f) return false;
    float inter = iw * ih;
    float u = (aa + ba) - inter;
    if (inter > thrHi * u) return true;
    if (inter < thrLo * u) return false;
    return __fdiv_rn(inter, u) > thr;
}

// block bitonic sort, descending, P = pow2 >= 256, P <= 8*TB
__device__ void bitonic_sort_desc(unsigned long long* a, int P)
{
    const int tid = threadIdx.x;
    for (int k = 2; k <= P; k <<= 1) {
        for (int j = k >> 1; j >= 256; j >>= 1) {
            for (int p = tid; p < P; p += TB) {
                int q = p ^ j;
                if (q > p) {
                    unsigned long long x = a[p], y = a[q];
                    bool dd = ((p & k) == 0);
                    if (dd ? (x < y) : (x > y)) { a[p] = y; a[q] = x; }
                }
            }
            __syncthreads();
        }
        for (int base = tid * 8; base < P; base += TB * 8) {
            unsigned long long v[8];
            #pragma unroll
            for (int i2 = 0; i2 < 8; i2++) v[i2] = a[base + i2];
            const bool up = ((base & k) == 0);
            int jtop = (k >> 1 < 128) ? (k >> 1) : 128;
            for (int j = jtop; j >= 8; j >>= 1) {
                int tj = j >> 3;
                bool keepMax = (up == ((tid & tj) == 0));
                #pragma unroll
                for (int i2 = 0; i2 < 8; i2++) {
                    unsigned long long pv = __shfl_xor_sync(FULLM, v[i2], tj);
                    if (keepMax ? (pv > v[i2]) : (pv < v[i2])) v[i2] = pv;
                }
            }
            int j0 = (k >> 1 < 4) ? (k >> 1) : 4;
            for (int j = j0; j > 0; j >>= 1) {
                #pragma unroll
                for (int i2 = 0; i2 < 8; i2++) {
                    int b2 = i2 ^ j;
                    if (b2 > i2) {
                        bool dd = (((base + i2) & k) == 0);
                        unsigned long long xx = v[i2], yy = v[b2];
                        if (dd ? (xx < yy) : (xx > yy)) { v[i2] = yy; v[b2] = xx; }
                    }
                }
            }
            #pragma unroll
            for (int i2 = 0; i2 < 8; i2++) a[base + i2] = v[i2];
        }
        __syncthreads();
    }
}

// ================= K1: histogram =========================================
__global__ void hist_kernel(const float* __restrict__ scores,
                            const float* __restrict__ confp,
                            int total, int c)
{
    __shared__ int hist[HBINS];
    const float conf = *confp;
    const int tid = threadIdx.x;
    for (int b = tid; b < HBINS; b += blockDim.x) hist[b] = 0;
    __syncthreads();
    if (conf < 1.0f) {
        const float scale = HBINS / (1.0f - conf);
        const int stride = gridDim.x * blockDim.x;
        for (int p = blockIdx.x * blockDim.x + tid; p < total; p += stride) {
            float v = scores[p];
            if (v > conf) {
                int j = p % c;
                if (j != 0) {
                    int b = (int)((v - conf) * scale);
                    b = max(0, min(HBINS - 1, b));
                    atomicAdd(&hist[b], 1);
                }
            }
        }
    }
    __syncthreads();
    for (int b = tid; b < HBINS; b += blockDim.x) {
        int h = hist[b];
        if (h) atomicAdd(&g_hist[b], h);
    }
}

// ================= K2: threshold from histogram ===========================
__global__ void thresh_kernel(const float* __restrict__ confp)
{
    __shared__ int hist[HBINS];
    __shared__ int chs[256];
    const int tid = threadIdx.x;
    for (int b = tid; b < HBINS; b += 256) hist[b] = g_hist[b];
    __syncthreads();
    {
        int sum = 0;
        for (int b = tid * 8; b < tid * 8 + 8; b++) sum += hist[b];
        chs[tid] = sum;
    }
    __syncthreads();
    if (tid == 0) {
        float conf = *confp;
        float step = (conf < 1.0f) ? (1.0f - conf) / HBINS : 0.f;
        int cum = 0, b300 = -1, bt = -1, cumAtT = 0;
        for (int ch = 255; ch >= 0; ch--) {
            int cs = chs[ch];
            int want = (b300 < 0) ? 384 : 1024;
            if (cum + cs >= want) {
                for (int b = ch * 8 + 7; b >= ch * 8; b--) {
                    cum += hist[b];
                    if (b300 < 0 && cum >= 384) b300 = b;
                    if (bt < 0 && cum >= 1024) { bt = b; cumAtT = cum; }
                }
            } else cum += cs;
            if (bt >= 0) break;
        }
        float t = conf, t3 = conf;
        if (step > 0.f && bt >= 0) {
            if (cumAtT > CAND_CAP && bt < HBINS - 1) bt += 1;  // huge tie bin
            t = conf + bt * step;
            if (t < conf) t = conf;
        }
        if (step > 0.f && b300 >= 0) t3 = conf + b300 * step;
        if (t3 < t) t3 = t;
        g_t = t; g_t300 = t3;
        g_nc = 0;
    }
    __syncthreads();
    for (int b = tid; b < HBINS; b += 256) g_hist[b] = 0;  // next replay
}

// ================= K3: compact survivors ==================================
__global__ void compact_kernel(const float* __restrict__ scores, int total, int c)
{
    const float t = g_t;
    const int lane = threadIdx.x & 31;
    const int stride = gridDim.x * blockDim.x;
    const int totR = ((total + stride - 1) / stride) * stride;
    for (int p = blockIdx.x * blockDim.x + threadIdx.x; p < totR; p += stride) {
        float v = (p < total) ? scores[p] : 0.f;
        bool ok = false;
        int j = 0;
        if (p < total && v > t) { j = p % c; ok = (j != 0); }
        unsigned bm = __ballot_sync(FULLM, ok);
        if (bm) {
            int base = 0;
            if (lane == 0) base = atomicAdd(&g_nc, __popc(bm));
            base = __shfl_sync(FULLM, base, 0);
            if (ok) {
                int slot = base + __popc(bm & ((1u << lane) - 1u));
                if (slot < CAND_CAP) {
                    int i = p / c;
                    g_cand[slot] = ((unsigned long long)(j - 1) << 45)
                                 | ((unsigned long long)__float_as_uint(v) << 13)
                                 | (unsigned)i;
                }
            }
        }
    }
}

// ============ block-wide chunked NMS over a sorted segment ================
// keys: (.. | scorebits<<13 | idx), sorted desc. Appends keeps to g_fb via sKc.
__device__ void block_nms_sorted(const unsigned long long* keys, int M, int cls,
                                 int n, float thr, float thrLo, float thrHi,
                                 const float4* __restrict__ bb4,
                                 float4* sbox, float* sarea,
                                 float4* kbox, float* karea,
                                 float4* cbox, float* carea,
                                 unsigned* sIntra, unsigned* snzw, unsigned* sSup32,
                                 int* sKc)
{
    __shared__ unsigned long long sKeptMask;
    __shared__ int sBase;
    const int tid = threadIdx.x, wid = tid >> 5, lane = tid & 31;
    const int PF = min(M, 1024);
    for (int p = tid; p < PF; p += TB) {
        float4 b = bb4[(unsigned)(keys[p] & 0x1FFFULL)];
        sbox[p]  = b;
        sarea[p] = (b.z - b.x) * (b.w - b.y);
    }
    __syncthreads();

    int pos = 0, nKept = 0;
    while (pos < M && nKept < MAXK) {
        const int nv = min(64, M - pos);
        if (tid < 64) {
            int cl2 = pos + tid;
            float4 cb = make_float4(0.f, 0.f, 0.f, 0.f);
            if (cl2 < M)
                cb = (cl2 < PF) ? sbox[cl2]
                                : bb4[(unsigned)(keys[cl2] & 0x1FFFULL)];
            cbox[tid]  = cb;
            carea[tid] = (cb.z - cb.x) * (cb.w - cb.y);
            if (tid < 2)  sSup32[tid] = 0;
            if (tid < 32) snzw[tid]   = 0;
        }
        __syncthreads();
        {
            // vs-kept: 32 warps -> group = wid&1, kept stride 16
            int cg = wid & 1;
            int cc = (cg << 5) | lane;
            float4 cb = cbox[cc];
            float  ca = carea[cc];
            bool sup = false;
            for (int k2 = wid >> 1; k2 < nKept; k2 += 16)
                sup |= iou_gt(kbox[k2], karea[k2], cb, ca, thr, thrLo, thrHi);
            unsigned bm = __ballot_sync(FULLM, sup);
            if (lane == 0 && bm) atomicOr(&sSup32[cg], bm);

            // intra rows: warp w owns rows 2w, 2w+1
            unsigned nzm = 0;
            #pragma unroll
            for (int r0 = 0; r0 < 2; r0++) {
                int r = (wid << 1) + r0;
                float4 rb = cbox[r];
                float  ra = carea[r];
                #pragma unroll
                for (int g = 0; g < 2; g++) {
                    int col = (g << 5) | lane;
                    bool pr = (col > r) &&
                              iou_gt(rb, ra, cbox[col], carea[col], thr, thrLo, thrHi);
                    unsigned w2 = __ballot_sync(FULLM, pr);
                    if (lane == 0) {
                        sIntra[r * 2 + g] = w2;
                        if (w2) nzm |= 1u << (r0 * 2 + g);
                    }
                }
            }
            if (lane == 0) snzw[wid] = nzm;
        }
        __syncthreads();

        if (tid == 0) {
            unsigned long long valid = (nv >= 64) ? ~0ULL : ((1ULL << nv) - 1ULL);
            unsigned long long sup = (((unsigned long long)sSup32[1] << 32) |
                                       sSup32[0]) | ~valid;
            unsigned long long nz = 0;
            #pragma unroll
            for (int w = 0; w < 32; w++) {
                unsigned mm = snzw[w];
                unsigned rowbits = 0;
                if (mm & 0x3u) rowbits |= 1u;
                if (mm & 0xCu) rowbits |= 2u;
                nz |= (unsigned long long)rowbits << (2 * w);
            }
            unsigned long long kept = 0;
            int prev = 0;
            while (nz) {
                int i = __ffsll((long long)nz) - 1;
                nz &= nz - 1;
                unsigned long long upto  = (i >= 63) ? ~0ULL : ((1ULL << (i + 1)) - 1ULL);
                unsigned long long fromp = (~0ULL) << prev;
                kept |= ~sup & upto & fromp;
                if (!((sup >> i) & 1ULL)) {
                    unsigned long long row =
                        (((unsigned long long)sIntra[2 * i + 1]) << 32) | sIntra[2 * i];
                    sup |= row;
                }
                prev = i + 1;
            }
            unsigned long long fromp = (prev >= 64) ? 0ULL : ((~0ULL) << prev);
            kept |= ~sup & fromp;
            sKeptMask = kept & valid;
        }
        __syncthreads();

        unsigned long long kept = sKeptMask;
        int nAdd = __popcll(kept);
        int capAdd = min(nAdd, MAXK - nKept);
        if (tid == 0) sBase = atomicAdd(sKc, capAdd);
        __syncthreads();
        if (tid < 64) {
            bool mk = (kept >> tid) & 1ULL;
            int before = __popcll(kept & ((1ULL << tid) - 1ULL));
            int myPos  = nKept + before;
            if (mk && myPos < MAXK) {
                kbox[myPos]  = cbox[tid];
                karea[myPos] = carea[tid];
                unsigned long long kk = keys[pos + tid];
                unsigned sb2  = (unsigned)((kk >> 13) & 0xFFFFFFFFULL);
                unsigned flat = (unsigned)(cls * n + (int)(kk & 0x1FFFULL));
                g_fb[sBase + before] =
                    ((unsigned long long)sb2 << 32) | (unsigned)(~flat);
            }
        }
        nKept = min(nKept + nAdd, MAXK);
        pos  += 64;
        __syncthreads();
    }
}

// ================= K4: sort + per-warp NMS + finalize =====================
__global__ __launch_bounds__(TB)
void process_kernel(const float4* __restrict__ bb4,
                    const float* __restrict__ scores,
                    const float* __restrict__ confp,
                    const float* __restrict__ nmsp,
                    float* __restrict__ out,
                    int n, int c, int nc)
{
    extern __shared__ unsigned char sm[];
    unsigned long long* ckey   = (unsigned long long*)sm;           // 4096*8
    unsigned long long* gkey   = (unsigned long long*)(sm + 32768); // 2048*8
    int*                hist   = (int*)(sm + 49152);                // 2048*4
    int*                schunk = (int*)(sm + 57344);                // 256*4
    unsigned long long* skey   = (unsigned long long*)sm;          // fb: 8192*8
    float4*   sbox   = (float4*)(sm + 65536);                      // 1024*16
    float*    sarea  = (float*)(sm + 81920);                       // 1024*4
    float4*   kbox   = (float4*)(sm + 86016);                      // 304*16
    float*    karea  = (float*)(sm + 90880);                       // 304*4
    float4*   cbox   = (float4*)(sm + 92096);                      // 64*16
    float*    carea  = (float*)(sm + 93120);                       // 64*4
    unsigned* sIntra = (unsigned*)(sm + 93376);                    // 128*4
    unsigned* snzw   = (unsigned*)(sm + 93888);                    // 32*4
    unsigned* sSup32 = (unsigned*)(sm + 94016);                    // 2*4

    __shared__ int clsStart[128], clsEnd[128], sFlag[128];
    __shared__ int sKc, sNFlag, sMf;
    __shared__ int sGc, sDone, sAbove, smaxbits;
    __shared__ float sLo, sHi, sCut;

    const int tid = threadIdx.x, wid = tid >> 5, lane = tid & 31;
    const float conf  = *confp;
    const float thr   = *nmsp;
    const float thrLo = thr * 0.9999f;
    const float thrHi = thr * 1.0001f;
    const float t     = g_t;
    const float t300  = g_t300;
    const int   G0raw = g_nc;
    const bool  candOvf = (G0raw > CAND_CAP);
    const int   G0    = min(G0raw, CAND_CAP);

    if (tid == 0) { sKc = 0; sNFlag = 0; }
    for (int i2 = tid; i2 < 128; i2 += TB) { clsStart[i2] = 0; clsEnd[i2] = 0; }

    int P = 256; while (P < G0) P <<= 1;
    for (int p = tid; p < P; p += TB) ckey[p] = (p < G0) ? g_cand[p] : 0ULL;
    __syncthreads();
    bitonic_sort_desc(ckey, P);

    // class segment boundaries
    for (int p = tid; p < G0; p += TB) {
        int cp    = (int)(ckey[p] >> 45);
        int cprev = (p == 0)      ? -1 : (int)(ckey[p - 1] >> 45);
        int cnext = (p == G0 - 1) ? -1 : (int)(ckey[p + 1] >> 45);
        if (cp != cprev) clsStart[cp] = p;
        if (cp != cnext) clsEnd[cp]   = p + 1;
    }
    __syncthreads();

    // per-warp NMS (M<=32 register path)
    for (int cls = wid; cls < nc; cls += TB / 32) {
        int st = clsStart[cls], M = clsEnd[cls] - st;
        if (M <= 0) continue;
        if (M > 32) {
            if (lane == 0) { int f = atomicAdd(&sNFlag, 1); sFlag[f] = cls; }
            continue;
        }
        unsigned long long kk = (lane < M) ? ckey[st + lane] : 0ULL;
        int idx = (int)(kk & 0x1FFFULL);
        float4 b = make_float4(0.f, 0.f, 0.f, 0.f);
        if (lane < M) b = bb4[idx];
        float ar = (b.z - b.x) * (b.w - b.y);
        unsigned myrow = 0;
        for (int j2 = 0; j2 < M - 1; j2++) {
            float4 bj;
            bj.x = __shfl_sync(FULLM, b.x, j2);
            bj.y = __shfl_sync(FULLM, b.y, j2);
            bj.z = __shfl_sync(FULLM, b.z, j2);
            bj.w = __shfl_sync(FULLM, b.w, j2);
            float aj = __shfl_sync(FULLM, ar, j2);
            bool pr = (lane > j2) && (lane < M) &&
                      iou_gt(bj, aj, b, ar, thr, thrLo, thrHi);
            unsigned bm = __ballot_sync(FULLM, pr);
            if (lane == j2) myrow = bm;
        }
        unsigned sup = 0, kept = 0;
        for (int j2 = 0; j2 < M; j2++) {
            unsigned rj = __shfl_sync(FULLM, myrow, j2);
            if (!((sup >> j2) & 1u)) { kept |= 1u << j2; sup |= rj; }
        }
        int cnt = __popc(kept);
        int base = 0;
        if (lane == 0) base = atomicAdd(&sKc, cnt);
        base = __shfl_sync(FULLM, base, 0);
        if ((kept >> lane) & 1u) {
            int slot = base + __popc(kept & ((1u << lane) - 1u));
            unsigned sb2  = (unsigned)((kk >> 13) & 0xFFFFFFFFULL);
            unsigned flat = (unsigned)(cls * n + idx);
            g_fb[slot] = ((unsigned long long)sb2 << 32) | (unsigned)(~flat);
        }
    }
    __syncthreads();

    // big classes: block path on sorted segment
    int nf = sNFlag;
    for (int f = 0; f < nf; f++) {
        int cls = sFlag[f];
        int st = clsStart[cls], M = clsEnd[cls] - st;
        block_nms_sorted(ckey + st, M, cls, n, thr, thrLo, thrHi, bb4,
                         sbox, sarea, kbox, karea, cbox, carea,
                         sIntra, snzw, sSup32, &sKc);
        __syncthreads();
    }
    __syncthreads();
    int G = sKc;

    // exact fallback (never expected): rerun everything at t = conf
    bool needFB = candOvf || (G < MAXK && t > conf);
    if (needFB) {
        if (tid == 0) sKc = 0;
        __syncthreads();
        for (int cls = 0; cls < nc; cls++) {
            if (tid == 0) sMf = 0;
            __syncthreads();
            const int col = cls + 1;
            const int nR = ((n + TB - 1) / TB) * TB;
            for (int i2 = tid; i2 < nR; i2 += TB) {
                float s = (i2 < n) ? scores[(size_t)i2 * c + col] : 0.f;
                bool ok = (i2 < n) && (s > conf);
                unsigned bm = __ballot_sync(FULLM, ok);
                if (bm) {
                    int base = 0;
                    if (lane == 0) base = atomicAdd(&sMf, __popc(bm));
                    base = __shfl_sync(FULLM, base, 0);
                    if (ok)
                        skey[base + __popc(bm & ((1u << lane) - 1u))] =
                            ((unsigned long long)__float_as_uint(s) << 13) | (unsigned)i2;
                }
            }
            __syncthreads();
            int M = sMf;
            if (M > 0) {
                int Pf = 256; while (Pf < M) Pf <<= 1;
                for (int p = M + tid; p < Pf; p += TB) skey[p] = 0ULL;
                __syncthreads();
                bitonic_sort_desc(skey, Pf);
                block_nms_sorted(skey, M, cls, n, thr, thrLo, thrHi, bb4,
                                 sbox, sarea, kbox, karea, cbox, carea,
                                 sIntra, snzw, sSup32, &sKc);
            }
            __syncthreads();
        }
        G = sKc;
    }

    // ---------------- finalize: top-300 + output ----------------
    if (tid == 0) { sGc = 0; sDone = 0; sAbove = 0; smaxbits = 0; }
    __syncthreads();

    // fast path: keeps >= t300
    {
        int cnt = 0;
        for (int s2 = tid; s2 < G; s2 += TB)
            if (__uint_as_float((unsigned)(g_fb[s2] >> 32)) >= t300) cnt++;
        for (int o = 16; o; o >>= 1) cnt += __shfl_xor_sync(FULLM, cnt, o);
        if (lane == 0 && cnt) atomicAdd(&sGc, cnt);
    }
    __syncthreads();
    const int fcnt = sGc;
    const bool fast = (fcnt >= MAXK && fcnt <= 512 && !needFB);
    float cutoff = t300;
    bool usecut = fast;
    int PS = fast ? 512 : 2048;

    if (!fast && G > 2048) {
        // histogram refine over g_fb scores to <=2048 survivors
        int mb = 0;
        for (int s2 = tid; s2 < G; s2 += TB)
            mb = max(mb, (int)(unsigned)(g_fb[s2] >> 32));
        for (int o = 16; o; o >>= 1) mb = max(mb, __shfl_xor_sync(FULLM, mb, o));
        if (lane == 0) atomicMax(&smaxbits, mb);
        __syncthreads();
        if (tid == 0) {
            sLo = conf;
            sHi = __int_as_float(smaxbits) * 1.0000002f + 1e-30f;
        }
        __syncthreads();
        for (int lev = 0; lev < 8; lev++) {
            if (sDone) break;
            for (int b = tid; b < 2048; b += TB) hist[b] = 0;
            __syncthreads();
            float L = sLo, H = sHi;
            float scale = 2048.0f / (H - L);
            for (int s2 = tid; s2 < G; s2 += TB) {
                float v = __uint_as_float((unsigned)(g_fb[s2] >> 32));
                if (v >= L && v < H) {
                    int b = (int)((v - L) * scale);
                    b = max(0, min(2047, b));
                    atomicAdd(&hist[b], 1);
                }
            }
            __syncthreads();
            if (tid < 256) {
                int sum = 0;
                for (int b = tid * 8; b < tid * 8 + 8; b++) sum += hist[b];
                schunk[tid] = sum;
            }
            __syncthreads();
            if (tid == 0) {
                int acc = sAbove, bstar = -1;
                for (int ch = 255; ch >= 0 && bstar < 0; ch--) {
                    if (acc + schunk[ch] < MAXK) { acc += schunk[ch]; }
                    else {
                        for (int b = ch * 8 + 7; b >= ch * 8; b--) {
                            if (acc + hist[b] < MAXK) acc += hist[b];
                            else { bstar = b; break; }
                        }
                    }
                }
                float w    = (H - L) / 2048.0f;
                float cutv = L + bstar * w;
                bool collapsed = !(w > 0.f) || (L + w == L);
                if (acc + hist[bstar] <= 2048 || lev == 7 || collapsed) {
                    float cut = cutv;
                    if (cut > 0.f) cut = __uint_as_float(__float_as_uint(cut) - 2);
                    sCut = cut; sDone = 1;
                } else {
                    sAbove = acc;
                    sLo = cutv;
                    sHi = L + (bstar + 1) * w;
                }
            }
            __syncthreads();
        }
        cutoff = sCut;
        usecut = true;
    }

    if (tid == 0) sGc = 0;
    __syncthreads();
    for (int s2 = tid; s2 < G; s2 += TB) {
        unsigned long long kk = g_fb[s2];
        float v = __uint_as_float((unsigned)(kk >> 32));
        if (!usecut || v >= cutoff) {
            int slot = atomicAdd(&sGc, 1);
            if (slot < PS) gkey[slot] = kk;
        }
    }
    __syncthreads();
    const int GG = min(sGc, PS);
    for (int p = GG + tid; p < PS; p += TB) gkey[p] = 0ULL;
    __syncthreads();
    bitonic_sort_desc(gkey, PS);

    const float* bbf = (const float*)bb4;
    for (int i = tid; i < MAXK; i += TB) {
        bool valid = (i < GG) && (gkey[i] != 0ULL);
        if (valid) {
            unsigned long long kk = gkey[i];
            float    s    = __uint_as_float((unsigned)(kk >> 32));
            unsigned flat = ~(unsigned)kk;
            int cc  = flat / n;
            int box = flat - cc * n;
            out[i * 5 + 0] = bbf[box * 4 + 0];
            out[i * 5 + 1] = bbf[box * 4 + 1];
            out[i * 5 + 2] = bbf[box * 4 + 2];
            out[i * 5 + 3] = bbf[box * 4 + 3];
            out[i * 5 + 4] = s;
            out[MAXK * 5 + i] = (float)(cc + 1);
        } else {
            out[i * 5 + 0] = 0.f; out[i * 5 + 1] = 0.f;
            out[i * 5 + 2] = 0.f; out[i * 5 + 3] = 0.f;
            out[i * 5 + 4] = 0.f;
            out[MAXK * 5 + i] = -1.0f;
        }
    }
}

// ================= launch =================================================
extern "C" void kernel_launch(void* const* d_in, const int* in_sizes, int n_in,
                              void* d_out, int out_size)
{
    const float* bboxes = (const float*)d_in[0];
    const float* scores = (const float*)d_in[1];
    const float* confp  = (const float*)d_in[2];
    const float* nmsp   = (const float*)d_in[3];

    int n  = in_sizes[0] / 4;
    int c  = in_sizes[1] / n;
    int nc = c - 1;
    int total = n * c;

    const int smemP = 94208;
    static bool attr_set = false;
    if (!attr_set) {
        cudaFuncSetAttribute(process_kernel,
                             cudaFuncAttributeMaxDynamicSharedMemorySize, smemP);
        attr_set = true;
    }

    hist_kernel<<<160, 256>>>(scores, confp, total, c);
    thresh_kernel<<<1, 256>>>(confp);
    compact_kernel<<<160, 256>>>(scores, total, c);
    process_kernel<<<1, TB, smemP>>>((const float4*)bboxes, scores, confp, nmsp,
                                     (float*)d_out, n, c, nc);
}

// round 14
// speedup vs baseline: 3.2104x; 3.2104x over previous
#include <cuda_runtime.h>
#include <math_constants.h>
#include <stdint.h>

// MulticlassNMS v7 — no single-block hot phase (defeats pSmIssueThrottle).
// K1 hist_kernel (160 blk):  2048-bin histogram of fg scores > conf.
// K2 thresh_kernel (1 blk):  scan hist -> g_t (~1024 survivors), g_t300
//                            (~384); reset state; pre-write default output.
// K3 compact_kernel (160 blk): scores > g_t -> per-class cells (<=32/class).
// K4 warp_nms_kernel (10 blk): 1 warp/class: shfl-sort <=32, register NMS,
//                            append keeps to g_fb, count keeps >= t300.
// K5 finalize_kernel (4 blk): rank-based (sort-free) top-300 write; exact
//                            single-block fallback on overflow (never taken).

#define MAXK  300
#define HBINS 2048
#define TB    1024
#define FULLM 0xffffffffu

__device__ int                g_hist[HBINS];
__device__ float              g_t, g_t300;
__device__ int                g_ccnt[128];
__device__ unsigned long long g_cell[128 * 32];
__device__ int                g_ovf;
__device__ int                g_kc, g_cnt300;
__device__ unsigned long long g_fb[24064];

// exact IoU>thr: multiply filter, __fdiv_rn fallback in ~1e-4 boundary band
__device__ __forceinline__ bool iou_gt(const float4 a, float aa,
                                       const float4 b, float ba,
                                       float thr, float thrLo, float thrHi)
{
    float ix1 = fmaxf(a.x, b.x), iy1 = fmaxf(a.y, b.y);
    float ix2 = fminf(a.z, b.z), iy2 = fminf(a.w, b.w);
    float iw = ix2 - ix1, ih = iy2 - iy1;
    if (iw <= 0.f || ih <= 0.f) return false;
    float inter = iw * ih;
    float u = (aa + ba) - inter;
    if (inter > thrHi * u) return true;
    if (inter < thrLo * u) return false;
    return __fdiv_rn(inter, u) > thr;
}

// block bitonic sort desc (fallback only), P pow2 in [256, 8192], 1024 thr
__device__ void bitonic_sort_desc(unsigned long long* a, int P)
{
    const int tid = threadIdx.x;
    for (int k = 2; k <= P; k <<= 1) {
        for (int j = k >> 1; j >= 256; j >>= 1) {
            for (int p = tid; p < P; p += TB) {
                int q = p ^ j;
                if (q > p) {
                    unsigned long long x = a[p], y = a[q];
                    bool dd = ((p & k) == 0);
                    if (dd ? (x < y) : (x > y)) { a[p] = y; a[q] = x; }
                }
            }
            __syncthreads();
        }
        for (int base = tid * 8; base < P; base += TB * 8) {
            unsigned long long v[8];
            #pragma unroll
            for (int i2 = 0; i2 < 8; i2++) v[i2] = a[base + i2];
            const bool up = ((base & k) == 0);
            int jtop = (k >> 1 < 128) ? (k >> 1) : 128;
            for (int j = jtop; j >= 8; j >>= 1) {
                int tj = j >> 3;
                bool keepMax = (up == ((tid & tj) == 0));
                #pragma unroll
                for (int i2 = 0; i2 < 8; i2++) {
                    unsigned long long pv = __shfl_xor_sync(FULLM, v[i2], tj);
                    if (keepMax ? (pv > v[i2]) : (pv < v[i2])) v[i2] = pv;
                }
            }
            int j0 = (k >> 1 < 4) ? (k >> 1) : 4;
            for (int j = j0; j > 0; j >>= 1) {
                #pragma unroll
                for (int i2 = 0; i2 < 8; i2++) {
                    int b2 = i2 ^ j;
                    if (b2 > i2) {
                        bool dd = (((base + i2) & k) == 0);
                        unsigned long long xx = v[i2], yy = v[b2];
                        if (dd ? (xx < yy) : (xx > yy)) { v[i2] = yy; v[b2] = xx; }
                    }
                }
            }
            #pragma unroll
            for (int i2 = 0; i2 < 8; i2++) a[base + i2] = v[i2];
        }
        __syncthreads();
    }
}

// ================= K1: histogram =========================================
__global__ void hist_kernel(const float* __restrict__ scores,
                            const float* __restrict__ confp,
                            int total, int c)
{
    __shared__ int hist[HBINS];
    const float conf = *confp;
    const int tid = threadIdx.x;
    for (int b = tid; b < HBINS; b += blockDim.x) hist[b] = 0;
    __syncthreads();
    if (conf < 1.0f) {
        const float scale = HBINS / (1.0f - conf);
        const int stride = gridDim.x * blockDim.x;
        for (int p = blockIdx.x * blockDim.x + tid; p < total; p += stride) {
            float v = scores[p];
            if (v > conf) {
                int j = p % c;
                if (j != 0) {
                    int b = (int)((v - conf) * scale);
                    b = max(0, min(HBINS - 1, b));
                    atomicAdd(&hist[b], 1);
                }
            }
        }
    }
    __syncthreads();
    for (int b = tid; b < HBINS; b += blockDim.x) {
        int h = hist[b];
        if (h) atomicAdd(&g_hist[b], h);
    }
}

// ================= K2: threshold + state reset + default output ===========
__global__ void thresh_kernel(const float* __restrict__ confp,
                              float* __restrict__ out)
{
    __shared__ int hist[HBINS];
    __shared__ int chs[256];
    const int tid = threadIdx.x;
    for (int b = tid; b < HBINS; b += 256) hist[b] = g_hist[b];
    __syncthreads();
    {
        int sum = 0;
        for (int b = tid * 8; b < tid * 8 + 8; b++) sum += hist[b];
        chs[tid] = sum;
    }
    __syncthreads();
    if (tid == 0) {
        float conf = *confp;
        float step = (conf < 1.0f) ? (1.0f - conf) / HBINS : 0.f;
        int cum = 0, b300 = -1, bt = -1, cumAtT = 0;
        for (int ch = 255; ch >= 0; ch--) {
            int cs = chs[ch];
            int want = (b300 < 0) ? 384 : 1024;
            if (cum + cs >= want) {
                for (int b = ch * 8 + 7; b >= ch * 8; b--) {
                    cum += hist[b];
                    if (b300 < 0 && cum >= 384) b300 = b;
                    if (bt < 0 && cum >= 1024) { bt = b; cumAtT = cum; }
                }
            } else cum += cs;
            if (bt >= 0) break;
        }
        float t = conf, t3 = conf;
        if (step > 0.f && bt >= 0) {
            if (cumAtT > 4096 && bt < HBINS - 1) bt += 1;  // huge tie bin
            t = conf + bt * step;
            if (t < conf) t = conf;
        }
        if (step > 0.f && b300 >= 0) t3 = conf + b300 * step;
        if (t3 < t) t3 = t;
        g_t = t; g_t300 = t3;
        g_kc = 0; g_cnt300 = 0; g_ovf = 0;
    }
    __syncthreads();
    for (int b = tid; b < HBINS; b += 256) g_hist[b] = 0;   // next replay
    for (int i = tid; i < 128; i += 256) g_ccnt[i] = 0;
    // default output: preds zeros, labels -1
    for (int i = tid; i < MAXK * 5; i += 256) out[i] = 0.f;
    for (int i = tid; i < MAXK; i += 256) out[MAXK * 5 + i] = -1.0f;
}

// ================= K3: compact into per-class cells =======================
__global__ void compact_kernel(const float* __restrict__ scores, int total, int c)
{
    const float t = g_t;
    const int stride = gridDim.x * blockDim.x;
    for (int p = blockIdx.x * blockDim.x + threadIdx.x; p < total; p += stride) {
        float v = scores[p];
        if (v > t) {
            int j = p % c;
            if (j != 0) {
                int cls = j - 1;
                int slot = atomicAdd(&g_ccnt[cls], 1);
                if (slot < 32) {
                    int i = p / c;
                    g_cell[cls * 32 + slot] =
                        ((unsigned long long)__float_as_uint(v) << 13) | (unsigned)i;
                } else g_ovf = 1;
            }
        }
    }
}

// ================= K4: one warp per class =================================
__global__ void warp_nms_kernel(const float4* __restrict__ bb4,
                                const float* __restrict__ nmsp,
                                int n, int nc)
{
    const int tid = threadIdx.x, wid = tid >> 5, lane = tid & 31;
    const int cls = blockIdx.x * (blockDim.x >> 5) + wid;
    if (cls >= nc) return;
    const int M = g_ccnt[cls];
    if (M <= 0 || M > 32) return;   // >32 -> g_ovf already set, fallback path
    const float thr = *nmsp;
    const float thrLo = thr * 0.9999f, thrHi = thr * 1.0001f;
    const float t300 = g_t300;

    unsigned long long v = (lane < M) ? g_cell[cls * 32 + lane] : 0ULL;
    // warp bitonic sort desc (ties: larger idx first via low-bit idx packing)
    #pragma unroll
    for (int k = 2; k <= 32; k <<= 1) {
        #pragma unroll
        for (int j = 16; j > 0; j >>= 1) {
            if (j < k) {
                unsigned long long pv = __shfl_xor_sync(FULLM, v, j);
                bool keepMax = (((lane & k) == 0) == ((lane & j) == 0));
                if ((pv > v) == keepMax) v = pv;
            }
        }
    }
    int idx = (int)(v & 0x1FFFULL);
    float4 b = make_float4(0.f, 0.f, 0.f, 0.f);
    if (lane < M) b = bb4[idx];
    float ar = (b.z - b.x) * (b.w - b.y);
    unsigned myrow = 0;
    for (int j2 = 0; j2 < M - 1; j2++) {
        float4 bj;
        bj.x = __shfl_sync(FULLM, b.x, j2);
        bj.y = __shfl_sync(FULLM, b.y, j2);
        bj.z = __shfl_sync(FULLM, b.z, j2);
        bj.w = __shfl_sync(FULLM, b.w, j2);
        float aj = __shfl_sync(FULLM, ar, j2);
        bool pr = (lane > j2) && (lane < M) &&
                  iou_gt(bj, aj, b, ar, thr, thrLo, thrHi);
        unsigned bm = __ballot_sync(FULLM, pr);
        if (lane == j2) myrow = bm;
    }
    unsigned sup = 0, kept = 0;
    for (int j2 = 0; j2 < M; j2++) {
        unsigned rj = __shfl_sync(FULLM, myrow, j2);
        if (!((sup >> j2) & 1u)) { kept |= 1u << j2; sup |= rj; }
    }
    int cnt = __popc(kept);
    int base = 0;
    if (lane == 0 && cnt) base = atomicAdd(&g_kc, cnt);
    base = __shfl_sync(FULLM, base, 0);
    unsigned sbits = (unsigned)(v >> 13);
    bool mine = (kept >> lane) & 1u;
    if (mine) {
        int slot = base + __popc(kept & ((1u << lane) - 1u));
        unsigned flat = (unsigned)(cls * n + idx);
        g_fb[slot] = ((unsigned long long)sbits << 32) | (unsigned)(~flat);
    }
    unsigned b3 = __ballot_sync(FULLM, mine && __uint_as_float(sbits) >= t300);
    if (lane == 0 && b3) atomicAdd(&g_cnt300, __popc(b3));
}

// ======= fallback helper: block-wide chunked NMS over a sorted segment ====
__device__ void block_nms_sorted(const unsigned long long* keys, int M, int cls,
                                 int n, float thr, float thrLo, float thrHi,
                                 const float4* __restrict__ bb4,
                                 float4* sbox, float* sarea,
                                 float4* kbox, float* karea,
                                 float4* cbox, float* carea,
                                 unsigned* sIntra, unsigned* snzw, unsigned* sSup32,
                                 int* sKc)
{
    __shared__ unsigned long long sKeptMask;
    __shared__ int sBase;
    const int tid = threadIdx.x, wid = tid >> 5, lane = tid & 31;
    const int PF = min(M, 1024);
    for (int p = tid; p < PF; p += TB) {
        float4 b = bb4[(unsigned)(keys[p] & 0x1FFFULL)];
        sbox[p]  = b;
        sarea[p] = (b.z - b.x) * (b.w - b.y);
    }
    __syncthreads();

    int pos = 0, nKept = 0;
    while (pos < M && nKept < MAXK) {
        const int nv = min(64, M - pos);
        if (tid < 64) {
            int cl2 = pos + tid;
            float4 cb = make_float4(0.f, 0.f, 0.f, 0.f);
            if (cl2 < M)
                cb = (cl2 < PF) ? sbox[cl2]
                                : bb4[(unsigned)(keys[cl2] & 0x1FFFULL)];
            cbox[tid]  = cb;
            carea[tid] = (cb.z - cb.x) * (cb.w - cb.y);
            if (tid < 2)  sSup32[tid] = 0;
            if (tid < 32) snzw[tid]   = 0;
        }
        __syncthreads();
        {
            int cg = wid & 1;
            int cc = (cg << 5) | lane;
            float4 cb = cbox[cc];
            float  ca = carea[cc];
            bool sup = false;
            for (int k2 = wid >> 1; k2 < nKept; k2 += 16)
                sup |= iou_gt(kbox[k2], karea[k2], cb, ca, thr, thrLo, thrHi);
            unsigned bm = __ballot_sync(FULLM, sup);
            if (lane == 0 && bm) atomicOr(&sSup32[cg], bm);

            unsigned nzm = 0;
            #pragma unroll
            for (int r0 = 0; r0 < 2; r0++) {
                int r = (wid << 1) + r0;
                float4 rb = cbox[r];
                float  ra = carea[r];
                #pragma unroll
                for (int g = 0; g < 2; g++) {
                    int col = (g << 5) | lane;
                    bool pr = (col > r) &&
                              iou_gt(rb, ra, cbox[col], carea[col], thr, thrLo, thrHi);
                    unsigned w2 = __ballot_sync(FULLM, pr);
                    if (lane == 0) {
                        sIntra[r * 2 + g] = w2;
                        if (w2) nzm |= 1u << (r0 * 2 + g);
                    }
                }
            }
            if (lane == 0) snzw[wid] = nzm;
        }
        __syncthreads();

        if (tid == 0) {
            unsigned long long valid = (nv >= 64) ? ~0ULL : ((1ULL << nv) - 1ULL);
            unsigned long long sup = (((unsigned long long)sSup32[1] << 32) |
                                       sSup32[0]) | ~valid;
            unsigned long long nz = 0;
            #pragma unroll
            for (int w = 0; w < 32; w++) {
                unsigned mm = snzw[w];
                unsigned rowbits = 0;
                if (mm & 0x3u) rowbits |= 1u;
                if (mm & 0xCu) rowbits |= 2u;
                nz |= (unsigned long long)rowbits << (2 * w);
            }
            unsigned long long kept = 0;
            int prev = 0;
            while (nz) {
                int i = __ffsll((long long)nz) - 1;
                nz &= nz - 1;
                unsigned long long upto  = (i >= 63) ? ~0ULL : ((1ULL << (i + 1)) - 1ULL);
                unsigned long long fromp = (~0ULL) << prev;
                kept |= ~sup & upto & fromp;
                if (!((sup >> i) & 1ULL)) {
                    unsigned long long row =
                        (((unsigned long long)sIntra[2 * i + 1]) << 32) | sIntra[2 * i];
                    sup |= row;
                }
                prev = i + 1;
            }
            unsigned long long fromp = (prev >= 64) ? 0ULL : ((~0ULL) << prev);
            kept |= ~sup & fromp;
            sKeptMask = kept & valid;
        }
        __syncthreads();

        unsigned long long kept = sKeptMask;
        int nAdd = __popcll(kept);
        int capAdd = min(nAdd, MAXK - nKept);
        if (tid == 0) sBase = atomicAdd(sKc, capAdd);
        __syncthreads();
        if (tid < 64) {
            bool mk = (kept >> tid) & 1ULL;
            int before = __popcll(kept & ((1ULL << tid) - 1ULL));
            int myPos  = nKept + before;
            if (mk && myPos < MAXK) {
                kbox[myPos]  = cbox[tid];
                karea[myPos] = carea[tid];
                unsigned long long kk = keys[pos + tid];
                unsigned sb2  = (unsigned)((kk >> 13) & 0xFFFFFFFFULL);
                unsigned flat = (unsigned)(cls * n + (int)(kk & 0x1FFFULL));
                g_fb[sBase + before] =
                    ((unsigned long long)sb2 << 32) | (unsigned)(~flat);
            }
        }
        nKept = min(nKept + nAdd, MAXK);
        pos  += 64;
        __syncthreads();
    }
}

// ================= K5: rank-based finalize (4 blocks) =====================
__global__ __launch_bounds__(TB)
void finalize_kernel(const float4* __restrict__ bb4,
                     const float* __restrict__ scores,
                     const float* __restrict__ confp,
                     const float* __restrict__ nmsp,
                     float* __restrict__ out,
                     int n, int c, int nc)
{
    extern __shared__ unsigned char sm[];
    const int tid = threadIdx.x, wid = tid >> 5, lane = tid & 31;
    const float conf  = *confp;
    const float thr   = *nmsp;
    const float thrLo = thr * 0.9999f;
    const float thrHi = thr * 1.0001f;
    const int   G      = g_kc;
    const int   cnt300 = g_cnt300;
    const int   ovf    = g_ovf;
    const float t      = g_t;
    const float t300   = g_t300;
    const float* bbf = (const float*)bb4;

    const bool useCut = (cnt300 >= MAXK);
    const int  S_sel  = useCut ? cnt300 : G;
    const bool fb = (ovf != 0) || (G < MAXK && t > conf) || (S_sel > 1024);

    if (!fb) {
        unsigned long long* skeys = (unsigned long long*)sm;   // [1024]
        __shared__ int sS;
        if (tid == 0) sS = 0;
        __syncthreads();
        for (int p = tid; p < G; p += TB) {
            unsigned long long kk = g_fb[p];
            float vv = __uint_as_float((unsigned)(kk >> 32));
            if (!useCut || vv >= t300) {
                int q = atomicAdd(&sS, 1);
                skeys[q] = kk;
            }
        }
        __syncthreads();
        const int S = sS;
        for (int p = tid; p < S; p += TB) {
            unsigned long long me = skeys[p];
            unsigned flat = ~(unsigned)me;
            if ((flat & 3u) != blockIdx.x) continue;
            int rank = 0;
            for (int q = 0; q < S; q++) rank += (skeys[q] > me) ? 1 : 0;
            if (rank < MAXK) {
                int cc  = flat / n;
                int box = flat - cc * n;
                out[rank * 5 + 0] = bbf[box * 4 + 0];
                out[rank * 5 + 1] = bbf[box * 4 + 1];
                out[rank * 5 + 2] = bbf[box * 4 + 2];
                out[rank * 5 + 3] = bbf[box * 4 + 3];
                out[rank * 5 + 4] = __uint_as_float((unsigned)(me >> 32));
                out[MAXK * 5 + rank] = (float)(cc + 1);
            }
        }
        return;
    }

    // ======== exact fallback (block 0 only; never taken in practice) ======
    if (blockIdx.x != 0) return;

    unsigned long long* fkey = (unsigned long long*)sm;            // [8192]
    float4*   sbox   = (float4*)(sm + 65536);                      // [1024]
    float*    sarea  = (float*)(sm + 81920);                       // [1024]
    float4*   kbox   = (float4*)(sm + 86016);                      // [304]
    float*    karea  = (float*)(sm + 90880);                       // [304]
    float4*   cbox   = (float4*)(sm + 92096);                      // [64]
    float*    carea  = (float*)(sm + 93120);                       // [64]
    unsigned* sIntra = (unsigned*)(sm + 93376);                    // [128]
    unsigned* snzw   = (unsigned*)(sm + 93888);                    // [32]
    unsigned* sSup32 = (unsigned*)(sm + 94016);                    // [2]
    // post-NMS overlays (sbox region free by then)
    unsigned long long* gkey   = (unsigned long long*)(sm + 65536); // [2048]
    int*                hist2  = (int*)(sm + 81920);                // [2048]
    int*                schunk = (int*)(sm + 90112);                // [256]

    __shared__ int sKc2, sMf;
    __shared__ int sGc, sDone, sAbove, smaxbits;
    __shared__ float sLo, sHi, sCut;

    if (tid == 0) sKc2 = 0;
    __syncthreads();

    for (int cls = 0; cls < nc; cls++) {
        if (tid == 0) sMf = 0;
        __syncthreads();
        const int col = cls + 1;
        const int nR = ((n + TB - 1) / TB) * TB;
        for (int i2 = tid; i2 < nR; i2 += TB) {
            float s = (i2 < n) ? scores[(size_t)i2 * c + col] : 0.f;
            bool ok = (i2 < n) && (s > conf);
            unsigned bm = __ballot_sync(FULLM, ok);
            if (bm) {
                int base = 0;
                if (lane == 0) base = atomicAdd(&sMf, __popc(bm));
                base = __shfl_sync(FULLM, base, 0);
                if (ok)
                    fkey[base + __popc(bm & ((1u << lane) - 1u))] =
                        ((unsigned long long)__float_as_uint(s) << 13) | (unsigned)i2;
            }
        }
        __syncthreads();
        int M = sMf;
        if (M > 0) {
            int Pf = 256; while (Pf < M) Pf <<= 1;
            for (int p = M + tid; p < Pf; p += TB) fkey[p] = 0ULL;
            __syncthreads();
            bitonic_sort_desc(fkey, Pf);
            block_nms_sorted(fkey, M, cls, n, thr, thrLo, thrHi, bb4,
                             sbox, sarea, kbox, karea, cbox, carea,
                             sIntra, snzw, sSup32, &sKc2);
        }
        __syncthreads();
    }
    const int G2 = sKc2;

    // selection: hist refine if needed, gather, sort 2048, write
    if (tid == 0) { sGc = 0; sDone = 0; sAbove = 0; smaxbits = 0; }
    __syncthreads();
    float cutoff = -CUDART_INF_F;
    bool usecut = false;
    if (G2 > 2048) {
        int mb = 0;
        for (int s2 = tid; s2 < G2; s2 += TB)
            mb = max(mb, (int)(unsigned)(g_fb[s2] >> 32));
        for (int o = 16; o; o >>= 1) mb = max(mb, __shfl_xor_sync(FULLM, mb, o));
        if (lane == 0) atomicMax(&smaxbits, mb);
        __syncthreads();
        if (tid == 0) {
            sLo = conf;
            sHi = __int_as_float(smaxbits) * 1.0000002f + 1e-30f;
        }
        __syncthreads();
        for (int lev = 0; lev < 8; lev++) {
            if (sDone) break;
            for (int b = tid; b < 2048; b += TB) hist2[b] = 0;
            __syncthreads();
            float L = sLo, H = sHi;
            float scale = 2048.0f / (H - L);
            for (int s2 = tid; s2 < G2; s2 += TB) {
                float v = __uint_as_float((unsigned)(g_fb[s2] >> 32));
                if (v >= L && v < H) {
                    int b = (int)((v - L) * scale);
                    b = max(0, min(2047, b));
                    atomicAdd(&hist2[b], 1);
                }
            }
            __syncthreads();
            if (tid < 256) {
                int sum = 0;
                for (int b = tid * 8; b < tid * 8 + 8; b++) sum += hist2[b];
                schunk[tid] = sum;
            }
            __syncthreads();
            if (tid == 0) {
                int acc = sAbove, bstar = -1;
                for (int ch = 255; ch >= 0 && bstar < 0; ch--) {
                    if (acc + schunk[ch] < MAXK) { acc += schunk[ch]; }
                    else {
                        for (int b = ch * 8 + 7; b >= ch * 8; b--) {
                            if (acc + hist2[b] < MAXK) acc += hist2[b];
                            else { bstar = b; break; }
                        }
                    }
                }
                float w    = (H - L) / 2048.0f;
                float cutv = L + bstar * w;
                bool collapsed = !(w > 0.f) || (L + w == L);
                if (acc + hist2[bstar] <= 2048 || lev == 7 || collapsed) {
                    float cut = cutv;
                    if (cut > 0.f) cut = __uint_as_float(__float_as_uint(cut) - 2);
                    sCut = cut; sDone = 1;
                } else {
                    sAbove = acc;
                    sLo = cutv;
                    sHi = L + (bstar + 1) * w;
                }
            }
            __syncthreads();
        }
        cutoff = sCut;
        usecut = true;
    }
    for (int s2 = tid; s2 < G2; s2 += TB) {
        unsigned long long kk = g_fb[s2];
        float v = __uint_as_float((unsigned)(kk >> 32));
        if (!usecut || v >= cutoff) {
            int slot = atomicAdd(&sGc, 1);
            if (slot < 2048) gkey[slot] = kk;
        }
    }
    __syncthreads();
    const int GG = min(sGc, 2048);
    for (int p = GG + tid; p < 2048; p += TB) gkey[p] = 0ULL;
    __syncthreads();
    bitonic_sort_desc(gkey, 2048);

    for (int i = tid; i < MAXK; i += TB) {
        bool valid = (i < GG) && (gkey[i] != 0ULL);
        if (valid) {
            unsigned long long kk = gkey[i];
            float    s    = __uint_as_float((unsigned)(kk >> 32));
            unsigned flat = ~(unsigned)kk;
            int cc  = flat / n;
            int box = flat - cc * n;
            out[i * 5 + 0] = bbf[box * 4 + 0];
            out[i * 5 + 1] = bbf[box * 4 + 1];
            out[i * 5 + 2] = bbf[box * 4 + 2];
            out[i * 5 + 3] = bbf[box * 4 + 3];
            out[i * 5 + 4] = s;
            out[MAXK * 5 + i] = (float)(cc + 1);
        } else {
            out[i * 5 + 0] = 0.f; out[i * 5 + 1] = 0.f;
            out[i * 5 + 2] = 0.f; out[i * 5 + 3] = 0.f;
            out[i * 5 + 4] = 0.f;
            out[MAXK * 5 + i] = -1.0f;
        }
    }
}

// ================= launch =================================================
extern "C" void kernel_launch(void* const* d_in, const int* in_sizes, int n_in,
                              void* d_out, int out_size)
{
    const float* bboxes = (const float*)d_in[0];
    const float* scores = (const float*)d_in[1];
    const float* confp  = (const float*)d_in[2];
    const float* nmsp   = (const float*)d_in[3];

    int n  = in_sizes[0] / 4;
    int c  = in_sizes[1] / n;
    int nc = c - 1;
    int total = n * c;

    const int smemF = 94208;
    static bool attr_set = false;
    if (!attr_set) {
        cudaFuncSetAttribute(finalize_kernel,
                             cudaFuncAttributeMaxDynamicSharedMemorySize, smemF);
        attr_set = true;
    }

    int nb4 = (nc + 7) / 8;
    hist_kernel<<<160, 256>>>(scores, confp, total, c);
    thresh_kernel<<<1, 256>>>(confp, (float*)d_out);
    compact_kernel<<<160, 256>>>(scores, total, c);
    warp_nms_kernel<<<nb4, 256>>>((const float4*)bboxes, nmsp, n, nc);
    finalize_kernel<<<4, TB, smemF>>>((const float4*)bboxes, scores, confp, nmsp,
                                      (float*)d_out, n, c, nc);
}